// round 15
// baseline (speedup 1.0000x reference)
#include <cuda_runtime.h>
#include <cuda_bf16.h>
#include <math.h>
#include <stdint.h>

// Problem constants
#define TT   4096
#define DD   2560
#define NH   8
#define KH   4
#define HD   256
#define WIN  1024

// ---------------- scratch (device globals; allocation-free rule) ----------------
__device__ __align__(256) float         g_QKV[TT * 4096];   // [t][j] fp32 (q|k|v) pre-norm
__device__ __align__(256) __nv_bfloat16 g_QKVh[TT * 4096];  // post norm/rope, bf16 hi
__device__ __align__(256) __nv_bfloat16 g_QKVl[TT * 4096];  // post norm/rope, bf16 lo
__device__ __align__(256) __nv_bfloat16 g_Xhi[TT * DD];     // x concat, bf16 hi
__device__ __align__(256) __nv_bfloat16 g_Xlo[TT * DD];
__device__ __align__(256) __nv_bfloat16 g_Whi[4096 * DD];   // qkv W, [j][d]
__device__ __align__(256) __nv_bfloat16 g_Wlo[4096 * DD];
__device__ __align__(256) __nv_bfloat16 g_W2hi[DD * 2048];  // out W, [d][nh]
__device__ __align__(256) __nv_bfloat16 g_W2lo[DD * 2048];
__device__ __align__(256) __nv_bfloat16 g_Ehi[TT * 2048];   // attention out, hi
__device__ __align__(256) __nv_bfloat16 g_Elo[TT * 2048];
__device__ __align__(256) float         g_SIN[TT * 128];
__device__ __align__(256) float         g_COS[TT * 128];

// ================= helpers =================
__device__ __forceinline__ uint32_t smem_u32(const void* p) {
    uint32_t a;
    asm("{ .reg .u64 t; cvta.to.shared.u64 t, %1; cvt.u32.u64 %0, t; }"
        : "=r"(a) : "l"(p));
    return a;
}

__device__ __forceinline__ void bf16_split(float v, __nv_bfloat16& h, __nv_bfloat16& l) {
    h = __float2bfloat16(v);
    l = __float2bfloat16(v - __bfloat162float(h));
}

__device__ __forceinline__ uint32_t pack2_hi(float a, float b) {
    return ((uint32_t)__bfloat16_as_ushort(__float2bfloat16(b)) << 16)
         | (uint32_t)__bfloat16_as_ushort(__float2bfloat16(a));
}

__device__ __forceinline__ void ldmx4(uint32_t* r, uint32_t addr) {
    asm volatile("ldmatrix.sync.aligned.m8n8.x4.shared.b16 {%0,%1,%2,%3}, [%4];"
                 : "=r"(r[0]), "=r"(r[1]), "=r"(r[2]), "=r"(r[3]) : "r"(addr));
}

__device__ __forceinline__ void ldmx4t(uint32_t* r, uint32_t addr) {
    asm volatile("ldmatrix.sync.aligned.m8n8.x4.trans.shared.b16 {%0,%1,%2,%3}, [%4];"
                 : "=r"(r[0]), "=r"(r[1]), "=r"(r[2]), "=r"(r[3]) : "r"(addr));
}

__device__ __forceinline__ void mma16816(float* c, const uint32_t* a, const uint32_t* b) {
    asm volatile(
        "mma.sync.aligned.m16n8k16.row.col.f32.bf16.bf16.f32 "
        "{%0,%1,%2,%3}, {%4,%5,%6,%7}, {%8,%9}, {%0,%1,%2,%3};"
        : "+f"(c[0]), "+f"(c[1]), "+f"(c[2]), "+f"(c[3])
        : "r"(a[0]), "r"(a[1]), "r"(a[2]), "r"(a[3]), "r"(b[0]), "r"(b[1]));
}

__device__ __forceinline__ void cp16(uint32_t sdst, const void* gsrc) {
    asm volatile("cp.async.cg.shared.global [%0], [%1], 16;"
                 :: "r"(sdst), "l"(gsrc) : "memory");
}

// ================= prep kernels =================
__global__ void convert_x_kernel(const float* __restrict__ x1, const float* __restrict__ x2,
                                 __nv_bfloat16* __restrict__ xh, __nv_bfloat16* __restrict__ xl)
{
    int t = blockIdx.x;
    const float* src = (t < 2048) ? (x1 + (size_t)t * DD) : (x2 + (size_t)(t - 2048) * DD);
    for (int c = threadIdx.x; c < DD; c += 256) {
        __nv_bfloat16 h, l;
        bf16_split(src[c], h, l);
        xh[(size_t)t * DD + c] = h;
        xl[(size_t)t * DD + c] = l;
    }
}

// qkv weights: 16 mats [D][H] -> W [j=4096][d=2560]
__global__ void transpose_qkvw_kernel(const float* __restrict__ qw,
                                      const float* __restrict__ kvw,
                                      __nv_bfloat16* __restrict__ wh,
                                      __nv_bfloat16* __restrict__ wl)
{
    __shared__ float tile[32][33];
    int m = blockIdx.z;
    const float* src = (m < 8) ? (qw + (size_t)m * DD * HD)
                               : (kvw + (size_t)(m - 8) * DD * HD);
    int jbase = (m < 8) ? (m << 8) : (2048 + ((m - 8) << 8));
    int d0 = blockIdx.x << 5, h0 = blockIdx.y << 5;
    int tx = threadIdx.x, ty = threadIdx.y;
#pragma unroll
    for (int i = 0; i < 4; i++) {
        int r = (ty << 2) + i;
        tile[r][tx] = src[(size_t)(d0 + r) * HD + h0 + tx];
    }
    __syncthreads();
#pragma unroll
    for (int i = 0; i < 4; i++) {
        int r = (ty << 2) + i;
        float v = tile[tx][r];
        __nv_bfloat16 h, l; bf16_split(v, h, l);
        size_t o = (size_t)(jbase + h0 + r) * DD + d0 + tx;
        wh[o] = h; wl[o] = l;
    }
}

// out weights: [2048=nh][2560=d] -> W2 [d][nh]
__global__ void transpose_outw_kernel(const float* __restrict__ ow,
                                      __nv_bfloat16* __restrict__ wh,
                                      __nv_bfloat16* __restrict__ wl)
{
    __shared__ float tile[32][33];
    int d0 = blockIdx.x << 5, n0 = blockIdx.y << 5;
    int tx = threadIdx.x, ty = threadIdx.y;
#pragma unroll
    for (int i = 0; i < 4; i++) {
        int r = (ty << 2) + i;
        tile[r][tx] = ow[(size_t)(n0 + r) * DD + d0 + tx];
    }
    __syncthreads();
#pragma unroll
    for (int i = 0; i < 4; i++) {
        int r = (ty << 2) + i;
        float v = tile[tx][r];
        __nv_bfloat16 h, l; bf16_split(v, h, l);
        size_t o = (size_t)(d0 + r) * 2048 + n0 + tx;
        wh[o] = h; wl[o] = l;
    }
}

// rope table: fp32 angle (matches reference), double range-reduction, fp32 sin/cos
__global__ void rope_table_kernel(const int* __restrict__ positions,
                                  float* __restrict__ st, float* __restrict__ ct)
{
    int idx = blockIdx.x * blockDim.x + threadIdx.x;   // 4096*128
    int t = idx >> 7;
    int i = idx & 127;
    float posf = (float)positions[t];
    float ts = (float)pow(10000.0, (double)i * (1.0 / 128.0));
    float ang = posf / ts;                         // fp32, like reference
    double da = (double)ang;
    double k = rint(da * 0.15915494309189533576888376337251);
    float rf = (float)(da - k * 6.2831853071795864769252867665590);
    st[idx] = sinf(rf);
    ct[idx] = cosf(rf);
}

// ================= mma.sync split-3 bf16 GEMM (unchanged from R11) =================
#define TSTRIDE 80
#define TBYTES  (128 * TSTRIDE)
#define STAGEB  (4 * TBYTES)
#define GEMM_SMEM (2 * STAGEB)

__device__ __forceinline__ void gemm_load_stage(
    uint32_t stage, int tid,
    const char* sAh, const char* sAl, const char* sBh, const char* sBl,
    size_t rowb, int k0b)
{
#pragma unroll
    for (int j = 0; j < 8; j++) {
        const char* sp = (j < 2) ? sAh : (j < 4) ? sAl : (j < 6) ? sBh : sBl;
        int idx = ((j & 1) << 8) + tid;
        int r = idx >> 2, c = idx & 3;
        uint32_t sdst = stage + (j >> 1) * TBYTES + r * TSTRIDE + (c << 4);
        cp16(sdst, sp + (size_t)r * rowb + k0b + (c << 4));
    }
    asm volatile("cp.async.commit_group;" ::: "memory");
}

__global__ __launch_bounds__(256) void mma_gemm_kernel(
    const __nv_bfloat16* __restrict__ Ahi, const __nv_bfloat16* __restrict__ Alo,
    const __nv_bfloat16* __restrict__ Bhi, const __nv_bfloat16* __restrict__ Blo,
    float* __restrict__ C, int ldc, int Kd)
{
    extern __shared__ char smem[];
    const uint32_t sbase = smem_u32(smem);
    const int tid = threadIdx.x;
    const int wid = tid >> 5, lane = tid & 31;
    const int warp_m = wid & 1, warp_n = wid >> 1;

    const int brow = blockIdx.y << 7;
    const int bcol = blockIdx.x << 7;
    const size_t rowb = (size_t)Kd * 2;
    const char* sAh = (const char*)Ahi + (size_t)brow * rowb;
    const char* sAl = (const char*)Alo + (size_t)brow * rowb;
    const char* sBh = (const char*)Bhi + (size_t)bcol * rowb;
    const char* sBl = (const char*)Blo + (size_t)bcol * rowb;

    const uint32_t rowA_off =
        (uint32_t)(warp_m * 64 + ((lane >> 3) & 1) * 8 + (lane & 7)) * TSTRIDE
        + ((lane >> 4) & 1) * 16;
    const uint32_t rowB_off =
        (uint32_t)(warp_n * 32 + ((lane >> 4) & 1) * 8 + (lane & 7)) * TSTRIDE
        + ((lane >> 3) & 1) * 16;

    float acc[4][4][4];
#pragma unroll
    for (int mt = 0; mt < 4; mt++)
#pragma unroll
        for (int nt = 0; nt < 4; nt++)
#pragma unroll
            for (int q = 0; q < 4; q++) acc[mt][nt][q] = 0.f;

    const int nsteps = Kd >> 5;
    gemm_load_stage(sbase, tid, sAh, sAl, sBh, sBl, rowb, 0);

    for (int s = 0; s < nsteps; s++) {
        if (s + 1 < nsteps) {
            gemm_load_stage(sbase + ((s + 1) & 1) * STAGEB, tid,
                            sAh, sAl, sBh, sBl, rowb, (s + 1) << 6);
            asm volatile("cp.async.wait_group 1;" ::: "memory");
        } else {
            asm volatile("cp.async.wait_group 0;" ::: "memory");
        }
        __syncthreads();

        const uint32_t stage = sbase + (s & 1) * STAGEB;
#pragma unroll
        for (int ks = 0; ks < 2; ks++) {
            uint32_t ah[4][4], al[4][4];
#pragma unroll
            for (int mt = 0; mt < 4; mt++) {
                uint32_t a = stage + rowA_off + mt * (16 * TSTRIDE) + ks * 32;
                ldmx4(ah[mt], a);
                ldmx4(al[mt], a + TBYTES);
            }
            uint32_t bh[2][4], bl[2][4];
#pragma unroll
            for (int p = 0; p < 2; p++) {
                uint32_t b = stage + 2 * TBYTES + rowB_off + p * (16 * TSTRIDE) + ks * 32;
                ldmx4(bh[p], b);
                ldmx4(bl[p], b + TBYTES);
            }
#pragma unroll
            for (int mt = 0; mt < 4; mt++)
#pragma unroll
                for (int nt = 0; nt < 4; nt++) {
                    const uint32_t* bhp = &bh[nt >> 1][(nt & 1) * 2];
                    const uint32_t* blp = &bl[nt >> 1][(nt & 1) * 2];
                    mma16816(acc[mt][nt], ah[mt], bhp);
                    mma16816(acc[mt][nt], ah[mt], blp);
                    mma16816(acc[mt][nt], al[mt], bhp);
                }
        }
        __syncthreads();
    }

    const int grp = lane >> 2, qid = lane & 3;
#pragma unroll
    for (int mt = 0; mt < 4; mt++) {
#pragma unroll
        for (int nt = 0; nt < 4; nt++) {
            int row = brow + warp_m * 64 + mt * 16 + grp;
            int col = bcol + warp_n * 32 + nt * 8 + qid * 2;
            *(float2*)&C[(size_t)row * ldc + col] =
                make_float2(acc[mt][nt][0], acc[mt][nt][1]);
            *(float2*)&C[(size_t)(row + 8) * ldc + col] =
                make_float2(acc[mt][nt][2], acc[mt][nt][3]);
        }
    }
}

// ================= RMSNorm + RoPE + bf16 split (one warp per (t,head-slot)) =================
// hh 0..7: q heads (norm+rope+1/16), 8..11: k heads (norm+rope), 12..15: v heads (split only)
__global__ void norm_rope_kernel(const float* __restrict__ qkv,
                                 const float* __restrict__ qns,
                                 const float* __restrict__ kns,
                                 const float* __restrict__ st,
                                 const float* __restrict__ ct,
                                 __nv_bfloat16* __restrict__ oh,
                                 __nv_bfloat16* __restrict__ ol)
{
    int g = blockIdx.x * 8 + (threadIdx.x >> 5);
    int lane = threadIdx.x & 31;
    int t = g >> 4;
    int hh = g & 15;
    int i4 = lane << 2;

    if (hh >= 12) {                                 // v: plain split
        int colbase = 3072 + ((hh - 12) << 8);
        const float* row = qkv + (size_t)t * 4096 + colbase;
        size_t ob = (size_t)t * 4096 + colbase;
#pragma unroll
        for (int half = 0; half < 2; half++) {
            float4 f = *(const float4*)&row[half * 128 + i4];
            float v[4] = { f.x, f.y, f.z, f.w };
            uint32_t hlo[2], llo[2];
#pragma unroll
            for (int p = 0; p < 2; p++) {
                __nv_bfloat16 h0, l0, h1, l1;
                bf16_split(v[p * 2], h0, l0);
                bf16_split(v[p * 2 + 1], h1, l1);
                hlo[p] = ((uint32_t)__bfloat16_as_ushort(h1) << 16) | __bfloat16_as_ushort(h0);
                llo[p] = ((uint32_t)__bfloat16_as_ushort(l1) << 16) | __bfloat16_as_ushort(l0);
            }
            *(uint2*)&oh[ob + half * 128 + i4] = make_uint2(hlo[0], hlo[1]);
            *(uint2*)&ol[ob + half * 128 + i4] = make_uint2(llo[0], llo[1]);
        }
        return;
    }

    bool isq = hh < 8;
    int colbase = isq ? (hh << 8) : (2048 + ((hh - 8) << 8));
    const float* sc = isq ? qns : kns;
    const float* row = qkv + (size_t)t * 4096 + colbase;

    float4 f = *(const float4*)&row[i4];
    float4 s = *(const float4*)&row[128 + i4];
    float ss = f.x * f.x + f.y * f.y + f.z * f.z + f.w * f.w
             + s.x * s.x + s.y * s.y + s.z * s.z + s.w * s.w;
#pragma unroll
    for (int off = 16; off; off >>= 1) ss += __shfl_xor_sync(0xffffffffu, ss, off);
    float mean = ss * (1.f / 256.f);
    float inv = (float)(1.0 / sqrt((double)mean + 1e-6));

    float4 scf = *(const float4*)&sc[i4];
    float4 scs = *(const float4*)&sc[128 + i4];
    float4 sa = *(const float4*)&st[(t << 7) + i4];
    float4 ca = *(const float4*)&ct[(t << 7) + i4];

    float fn[4] = { f.x * inv * (1.f + scf.x), f.y * inv * (1.f + scf.y),
                    f.z * inv * (1.f + scf.z), f.w * inv * (1.f + scf.w) };
    float sn[4] = { s.x * inv * (1.f + scs.x), s.y * inv * (1.f + scs.y),
                    s.z * inv * (1.f + scs.z), s.w * inv * (1.f + scs.w) };
    float saa[4] = { sa.x, sa.y, sa.z, sa.w };
    float caa[4] = { ca.x, ca.y, ca.z, ca.w };
    float qm = isq ? 0.0625f : 1.0f;
    float o1[4], o2[4];
#pragma unroll
    for (int k = 0; k < 4; k++) {
        o1[k] = (fn[k] * caa[k] - sn[k] * saa[k]) * qm;
        o2[k] = (sn[k] * caa[k] + fn[k] * saa[k]) * qm;
    }
    size_t ob = (size_t)t * 4096 + colbase;
    uint32_t h1lo[2], l1lo[2], h2lo[2], l2lo[2];
#pragma unroll
    for (int p = 0; p < 2; p++) {
        __nv_bfloat16 ha, la, hb, lb;
        bf16_split(o1[p * 2], ha, la); bf16_split(o1[p * 2 + 1], hb, lb);
        h1lo[p] = ((uint32_t)__bfloat16_as_ushort(hb) << 16) | __bfloat16_as_ushort(ha);
        l1lo[p] = ((uint32_t)__bfloat16_as_ushort(lb) << 16) | __bfloat16_as_ushort(la);
        bf16_split(o2[p * 2], ha, la); bf16_split(o2[p * 2 + 1], hb, lb);
        h2lo[p] = ((uint32_t)__bfloat16_as_ushort(hb) << 16) | __bfloat16_as_ushort(ha);
        l2lo[p] = ((uint32_t)__bfloat16_as_ushort(lb) << 16) | __bfloat16_as_ushort(la);
    }
    *(uint2*)&oh[ob + i4]       = make_uint2(h1lo[0], h1lo[1]);
    *(uint2*)&ol[ob + i4]       = make_uint2(l1lo[0], l1lo[1]);
    *(uint2*)&oh[ob + 128 + i4] = make_uint2(h2lo[0], h2lo[1]);
    *(uint2*)&ol[ob + 128 + i4] = make_uint2(l2lo[0], l2lo[1]);
}

// ================= tensor-core sliding-window flash attention =================
// BQ=64, BKV=32, 8 warps. S split-3 (Qh.Kh+Qh.Kl+Ql.Kh), PV split-3 (Ph.Vh+Ph.Vl+Pl.Vh).
#define QSTR 528                       // row stride bytes for Q/K/V smem tiles
#define O_QH 0
#define O_QL (O_QH + 64 * QSTR)
#define O_KH (O_QL + 64 * QSTR)
#define O_KL (O_KH + 32 * QSTR)
#define O_VH (O_KL + 32 * QSTR)
#define O_VL (O_VH + 32 * QSTR)
#define O_S  (O_VL + 32 * QSTR)        // 64 rows x 36 floats
#define O_PH (O_S + 64 * 144)
#define O_PL (O_PH + 64 * 80)
#define O_AL (O_PL + 64 * 80)
#define O_LL (O_AL + 256)
#define ATTN_SMEM (O_LL + 256)         // 155136

__global__ __launch_bounds__(256) void attn_kernel(
    const __nv_bfloat16* __restrict__ qkvh, const __nv_bfloat16* __restrict__ qkvl,
    __nv_bfloat16* __restrict__ ehi, __nv_bfloat16* __restrict__ elo)
{
    extern __shared__ char sm[];
    const uint32_t sb = smem_u32(sm);
    const int qt0  = blockIdx.x << 6;
    const int n    = blockIdx.y;
    const int kvh  = n >> 1;
    const int qcol = n << 8;
    const int kcol = 2048 + (kvh << 8);
    const int vcol = 3072 + (kvh << 8);
    const int tid = threadIdx.x;
    const int wid = tid >> 5, lane = tid & 31;
    const int warp_m = wid & 3;        // 16-row group
    const int warp_sn = wid >> 2;      // S: which 16-key half
    const int warp_vn = wid >> 2;      // PV: which 128-d half
    const int grp = lane >> 2, qid = lane & 3;
    const float NEGINF = __int_as_float(0xff800000u);

    // load Q (hi/lo)
    for (int u = tid; u < 2048; u += 256) {
        int r = u >> 5, c = (u & 31) << 4;
        size_t grow = (size_t)(qt0 + r) * 4096 + qcol;
        cp16(sb + O_QH + r * QSTR + c, (const char*)(qkvh + grow) + c);
        cp16(sb + O_QL + r * QSTR + c, (const char*)(qkvl + grow) + c);
    }
    asm volatile("cp.async.commit_group;\n\tcp.async.wait_group 0;" ::: "memory");

    // ldmatrix base addresses
    const uint32_t aQrow = (uint32_t)(warp_m * 16 + ((lane >> 3) & 1) * 8 + (lane & 7));
    const uint32_t aQhA = sb + O_QH + aQrow * QSTR + ((lane >> 4) & 1) * 16;
    const uint32_t aQlA = sb + O_QL + aQrow * QSTR + ((lane >> 4) & 1) * 16;
    const uint32_t bKkey = (uint32_t)(warp_sn * 16 + ((lane >> 4) & 1) * 8 + (lane & 7));
    const uint32_t bKhA = sb + O_KH + bKkey * QSTR + ((lane >> 3) & 1) * 16;
    const uint32_t bKlA = sb + O_KL + bKkey * QSTR + ((lane >> 3) & 1) * 16;
    const uint32_t aPhA = sb + O_PH + aQrow * 80 + ((lane >> 4) & 1) * 16;
    const uint32_t aPlA = sb + O_PL + aQrow * 80 + ((lane >> 4) & 1) * 16;
    const uint32_t bVkey = (uint32_t)(((lane >> 3) & 1) * 8 + (lane & 7));
    const uint32_t bVoff = (uint32_t)(warp_vn * 256) + ((lane >> 4) & 1) * 16;
    const uint32_t bVhA = sb + O_VH + bVkey * QSTR + bVoff;
    const uint32_t bVlA = sb + O_VL + bVkey * QSTR + bVoff;

    float accO[16][4];
#pragma unroll
    for (int nt = 0; nt < 16; nt++)
#pragma unroll
        for (int q = 0; q < 4; q++) accO[nt][q] = 0.f;

    // softmax thread state: row = tid>>2, quad lane sq = tid&3 (keys sq*8..sq*8+7)
    const int srow = tid >> 2, sq = tid & 3;
    float m_run = -1e30f, l_run = 0.f;
    float* sS = (float*)(sm + O_S);
    float* sAl = (float*)(sm + O_AL);
    float* sLl = (float*)(sm + O_LL);

    int s_lo = qt0 - (WIN - 1); if (s_lo < 0) s_lo = 0;
    int ks0 = s_lo & ~31;

    for (int ks = ks0; ks < qt0 + 64; ks += 32) {
        __syncthreads();   // prior PV readers done (also covers Q visibility, iter 0)
        for (int u = tid; u < 1024; u += 256) {
            int r = u >> 5, c = (u & 31) << 4;
            size_t grow = (size_t)(ks + r) * 4096;
            cp16(sb + O_KH + r * QSTR + c, (const char*)(qkvh + grow + kcol) + c);
            cp16(sb + O_KL + r * QSTR + c, (const char*)(qkvl + grow + kcol) + c);
            cp16(sb + O_VH + r * QSTR + c, (const char*)(qkvh + grow + vcol) + c);
            cp16(sb + O_VL + r * QSTR + c, (const char*)(qkvl + grow + vcol) + c);
        }
        asm volatile("cp.async.commit_group;\n\tcp.async.wait_group 0;" ::: "memory");
        __syncthreads();

        // ---- S = Q K^T (split-3), warp tile 16 rows x 16 keys ----
        float s0[4] = {0.f, 0.f, 0.f, 0.f}, s1[4] = {0.f, 0.f, 0.f, 0.f};
#pragma unroll
        for (int kk = 0; kk < 16; kk++) {
            uint32_t qh[4], ql[4], kh[4], kl[4];
            ldmx4(qh, aQhA + kk * 32);
            ldmx4(ql, aQlA + kk * 32);
            ldmx4(kh, bKhA + kk * 32);
            ldmx4(kl, bKlA + kk * 32);
            mma16816(s0, qh, &kh[0]); mma16816(s0, qh, &kl[0]); mma16816(s0, ql, &kh[0]);
            mma16816(s1, qh, &kh[2]); mma16816(s1, qh, &kl[2]); mma16816(s1, ql, &kh[2]);
        }
        {
            int r0 = warp_m * 16 + grp;
            int c0 = warp_sn * 16 + qid * 2;
            *(float2*)&sS[r0 * 36 + c0]           = make_float2(s0[0], s0[1]);
            *(float2*)&sS[(r0 + 8) * 36 + c0]     = make_float2(s0[2], s0[3]);
            *(float2*)&sS[r0 * 36 + c0 + 8]       = make_float2(s1[0], s1[1]);
            *(float2*)&sS[(r0 + 8) * 36 + c0 + 8] = make_float2(s1[2], s1[3]);
        }
        __syncthreads();

        // ---- online softmax (4 threads per row, 8 keys each) ----
        {
            float sv[8];
            const float* sp = &sS[srow * 36 + sq * 8];
            *(float4*)&sv[0] = *(const float4*)&sp[0];
            *(float4*)&sv[4] = *(const float4*)&sp[4];
            int tg = qt0 + srow;
            float mx = m_run;
#pragma unroll
            for (int j = 0; j < 8; j++) {
                int sg = ks + sq * 8 + j;
                bool ok = (sg <= tg) && (sg + WIN > tg);
                sv[j] = ok ? sv[j] : NEGINF;
                mx = fmaxf(mx, sv[j]);
            }
            mx = fmaxf(mx, __shfl_xor_sync(0xffffffffu, mx, 1));
            mx = fmaxf(mx, __shfl_xor_sync(0xffffffffu, mx, 2));
            float alpha = expf(m_run - mx);
            float psum = 0.f;
#pragma unroll
            for (int j = 0; j < 8; j += 2) {
                float p0 = expf(sv[j] - mx);
                float p1 = expf(sv[j + 1] - mx);
                psum += p0 + p1;
                __nv_bfloat16 h0, l0, h1, l1;
                bf16_split(p0, h0, l0);
                bf16_split(p1, h1, l1);
                uint32_t uh = ((uint32_t)__bfloat16_as_ushort(h1) << 16) | __bfloat16_as_ushort(h0);
                uint32_t ul = ((uint32_t)__bfloat16_as_ushort(l1) << 16) | __bfloat16_as_ushort(l0);
                int ob = srow * 80 + (sq * 8 + j) * 2;
                *(uint32_t*)(sm + O_PH + ob) = uh;
                *(uint32_t*)(sm + O_PL + ob) = ul;
            }
            psum += __shfl_xor_sync(0xffffffffu, psum, 1);
            psum += __shfl_xor_sync(0xffffffffu, psum, 2);
            l_run = l_run * alpha + psum;
            m_run = mx;
            if (sq == 0) { sAl[srow] = alpha; sLl[srow] = l_run; }
        }
        __syncthreads();

        // ---- PV: O = P V (split-3), warp tile 16 rows x 128 d ----
        {
            float a0 = sAl[warp_m * 16 + grp];
            float a1 = sAl[warp_m * 16 + grp + 8];
#pragma unroll
            for (int nt = 0; nt < 16; nt++) {
                accO[nt][0] *= a0; accO[nt][1] *= a0;
                accO[nt][2] *= a1; accO[nt][3] *= a1;
            }
#pragma unroll
            for (int kst = 0; kst < 2; kst++) {
                uint32_t ph_[4], pl_[4];
                ldmx4(ph_, aPhA + kst * 32);
                ldmx4(pl_, aPlA + kst * 32);
#pragma unroll
                for (int dt = 0; dt < 8; dt++) {
                    uint32_t vh_[4], vl_[4];
                    uint32_t va = kst * (16 * QSTR) + dt * 32;
                    ldmx4t(vh_, bVhA + va);
                    ldmx4t(vl_, bVlA + va);
                    mma16816(accO[dt * 2],     ph_, &vh_[0]);
                    mma16816(accO[dt * 2],     ph_, &vl_[0]);
                    mma16816(accO[dt * 2],     pl_, &vh_[0]);
                    mma16816(accO[dt * 2 + 1], ph_, &vh_[2]);
                    mma16816(accO[dt * 2 + 1], ph_, &vl_[2]);
                    mma16816(accO[dt * 2 + 1], pl_, &vh_[2]);
                }
            }
        }
    }

    // ---- epilogue: normalize and write bf16 hi/lo ENC ----
    float inv0 = 1.f / sLl[warp_m * 16 + grp];
    float inv1 = 1.f / sLl[warp_m * 16 + grp + 8];
    int row0 = qt0 + warp_m * 16 + grp;
#pragma unroll
    for (int nt = 0; nt < 16; nt++) {
        int dt = nt >> 1;
        int col = (n << 8) + warp_vn * 128 + dt * 16 + (nt & 1) * 8 + qid * 2;
        float v0 = accO[nt][0] * inv0, v1 = accO[nt][1] * inv0;
        float v2 = accO[nt][2] * inv1, v3 = accO[nt][3] * inv1;
        __nv_bfloat16 h0, l0, h1, l1;
        bf16_split(v0, h0, l0); bf16_split(v1, h1, l1);
        *(uint32_t*)&ehi[(size_t)row0 * 2048 + col] =
            ((uint32_t)__bfloat16_as_ushort(h1) << 16) | __bfloat16_as_ushort(h0);
        *(uint32_t*)&elo[(size_t)row0 * 2048 + col] =
            ((uint32_t)__bfloat16_as_ushort(l1) << 16) | __bfloat16_as_ushort(l0);
        bf16_split(v2, h0, l0); bf16_split(v3, h1, l1);
        *(uint32_t*)&ehi[(size_t)(row0 + 8) * 2048 + col] =
            ((uint32_t)__bfloat16_as_ushort(h1) << 16) | __bfloat16_as_ushort(h0);
        *(uint32_t*)&elo[(size_t)(row0 + 8) * 2048 + col] =
            ((uint32_t)__bfloat16_as_ushort(l1) << 16) | __bfloat16_as_ushort(l0);
    }
}

// ================= launch =================
extern "C" void kernel_launch(void* const* d_in, const int* in_sizes, int n_in,
                              void* d_out, int out_size)
{
    const float* x1   = (const float*)d_in[0];
    const float* x2   = (const float*)d_in[1];
    const float* qw   = (const float*)d_in[2];
    const float* kvw  = (const float*)d_in[3];
    const float* outw = (const float*)d_in[4];
    const float* qns  = (const float*)d_in[5];
    const float* kns  = (const float*)d_in[6];
    const int*   pos  = (const int*)d_in[7];
    float* out = (float*)d_out;

    float *pQKV, *pSIN, *pCOS;
    __nv_bfloat16 *pQKVh, *pQKVl, *pXh, *pXl, *pWh, *pWl, *pW2h, *pW2l, *pEh, *pEl;
    cudaGetSymbolAddress((void**)&pQKV,  g_QKV);
    cudaGetSymbolAddress((void**)&pQKVh, g_QKVh);
    cudaGetSymbolAddress((void**)&pQKVl, g_QKVl);
    cudaGetSymbolAddress((void**)&pSIN,  g_SIN);
    cudaGetSymbolAddress((void**)&pCOS,  g_COS);
    cudaGetSymbolAddress((void**)&pXh,   g_Xhi);
    cudaGetSymbolAddress((void**)&pXl,   g_Xlo);
    cudaGetSymbolAddress((void**)&pWh,   g_Whi);
    cudaGetSymbolAddress((void**)&pWl,   g_Wlo);
    cudaGetSymbolAddress((void**)&pW2h,  g_W2hi);
    cudaGetSymbolAddress((void**)&pW2l,  g_W2lo);
    cudaGetSymbolAddress((void**)&pEh,   g_Ehi);
    cudaGetSymbolAddress((void**)&pEl,   g_Elo);

    // prep
    convert_x_kernel<<<TT, 256>>>(x1, x2, pXh, pXl);
    transpose_qkvw_kernel<<<dim3(DD / 32, HD / 32, 16), dim3(32, 8)>>>(qw, kvw, pWh, pWl);
    transpose_outw_kernel<<<dim3(DD / 32, 2048 / 32), dim3(32, 8)>>>(outw, pW2h, pW2l);
    rope_table_kernel<<<(TT * 128) / 256, 256>>>(pos, pSIN, pCOS);

    // QKV projection (tensor cores, split-3)
    cudaFuncSetAttribute(mma_gemm_kernel, cudaFuncAttributeMaxDynamicSharedMemorySize,
                         GEMM_SMEM);
    mma_gemm_kernel<<<dim3(4096 / 128, TT / 128), 256, GEMM_SMEM>>>(
        pXh, pXl, pWh, pWl, pQKV, 4096, DD);

    // RMSNorm + RoPE + bf16 split (q,k normed+roped; v split only)
    norm_rope_kernel<<<(TT * 16) / 8, 256>>>(pQKV, qns, kns, pSIN, pCOS, pQKVh, pQKVl);

    // tensor-core sliding-window flash attention -> ENC bf16 hi/lo
    cudaFuncSetAttribute(attn_kernel, cudaFuncAttributeMaxDynamicSharedMemorySize,
                         ATTN_SMEM);
    attn_kernel<<<dim3(TT / 64, NH), 256, ATTN_SMEM>>>(pQKVh, pQKVl, pEh, pEl);

    // output projection (tensor cores, split-3)
    mma_gemm_kernel<<<dim3(DD / 128, TT / 128), 256, GEMM_SMEM>>>(
        pEh, pEl, pW2h, pW2l, out, DD, 2048);
}

// round 16
// speedup vs baseline: 1.0021x; 1.0021x over previous
#include <cuda_runtime.h>
#include <cuda_bf16.h>
#include <math.h>
#include <stdint.h>

// Problem constants
#define TT   4096
#define DD   2560
#define NH   8
#define KH   4
#define HD   256
#define WIN  1024

// ---------------- scratch (device globals; allocation-free rule) ----------------
__device__ __align__(256) float         g_QKV[TT * 4096];   // [t][j] fp32 (q|k|v) pre-norm
__device__ __align__(256) __nv_bfloat16 g_QKVh[TT * 4096];  // post norm/rope, bf16 hi
__device__ __align__(256) __nv_bfloat16 g_QKVl[TT * 4096];  // post norm/rope, bf16 lo
__device__ __align__(256) __nv_bfloat16 g_Xhi[TT * DD];     // x concat, bf16 hi
__device__ __align__(256) __nv_bfloat16 g_Xlo[TT * DD];
__device__ __align__(256) __nv_bfloat16 g_Whi[4096 * DD];   // qkv W, [j][d]
__device__ __align__(256) __nv_bfloat16 g_Wlo[4096 * DD];
__device__ __align__(256) __nv_bfloat16 g_W2hi[DD * 2048];  // out W, [d][nh]
__device__ __align__(256) __nv_bfloat16 g_W2lo[DD * 2048];
__device__ __align__(256) __nv_bfloat16 g_Ehi[TT * 2048];   // attention out, hi
__device__ __align__(256) __nv_bfloat16 g_Elo[TT * 2048];
__device__ __align__(256) float         g_SIN[TT * 128];
__device__ __align__(256) float         g_COS[TT * 128];

// ================= helpers =================
__device__ __forceinline__ uint32_t smem_u32(const void* p) {
    uint32_t a;
    asm("{ .reg .u64 t; cvta.to.shared.u64 t, %1; cvt.u32.u64 %0, t; }"
        : "=r"(a) : "l"(p));
    return a;
}

__device__ __forceinline__ void bf16_split(float v, __nv_bfloat16& h, __nv_bfloat16& l) {
    h = __float2bfloat16(v);
    l = __float2bfloat16(v - __bfloat162float(h));
}

__device__ __forceinline__ uint32_t pack2_hi(float a, float b) {
    return ((uint32_t)__bfloat16_as_ushort(__float2bfloat16(b)) << 16)
         | (uint32_t)__bfloat16_as_ushort(__float2bfloat16(a));
}

__device__ __forceinline__ void ldmx4(uint32_t* r, uint32_t addr) {
    asm volatile("ldmatrix.sync.aligned.m8n8.x4.shared.b16 {%0,%1,%2,%3}, [%4];"
                 : "=r"(r[0]), "=r"(r[1]), "=r"(r[2]), "=r"(r[3]) : "r"(addr));
}

__device__ __forceinline__ void ldmx4t(uint32_t* r, uint32_t addr) {
    asm volatile("ldmatrix.sync.aligned.m8n8.x4.trans.shared.b16 {%0,%1,%2,%3}, [%4];"
                 : "=r"(r[0]), "=r"(r[1]), "=r"(r[2]), "=r"(r[3]) : "r"(addr));
}

__device__ __forceinline__ void mma16816(float* c, const uint32_t* a, const uint32_t* b) {
    asm volatile(
        "mma.sync.aligned.m16n8k16.row.col.f32.bf16.bf16.f32 "
        "{%0,%1,%2,%3}, {%4,%5,%6,%7}, {%8,%9}, {%0,%1,%2,%3};"
        : "+f"(c[0]), "+f"(c[1]), "+f"(c[2]), "+f"(c[3])
        : "r"(a[0]), "r"(a[1]), "r"(a[2]), "r"(a[3]), "r"(b[0]), "r"(b[1]));
}

__device__ __forceinline__ void cp16(uint32_t sdst, const void* gsrc) {
    asm volatile("cp.async.cg.shared.global [%0], [%1], 16;"
                 :: "r"(sdst), "l"(gsrc) : "memory");
}

// ================= prep kernels =================
__global__ void convert_x_kernel(const float* __restrict__ x1, const float* __restrict__ x2,
                                 __nv_bfloat16* __restrict__ xh, __nv_bfloat16* __restrict__ xl)
{
    int t = blockIdx.x;
    const float* src = (t < 2048) ? (x1 + (size_t)t * DD) : (x2 + (size_t)(t - 2048) * DD);
    for (int c = threadIdx.x; c < DD; c += 256) {
        __nv_bfloat16 h, l;
        bf16_split(src[c], h, l);
        xh[(size_t)t * DD + c] = h;
        xl[(size_t)t * DD + c] = l;
    }
}

// qkv weights: 16 mats [D][H] -> W [j=4096][d=2560]
__global__ void transpose_qkvw_kernel(const float* __restrict__ qw,
                                      const float* __restrict__ kvw,
                                      __nv_bfloat16* __restrict__ wh,
                                      __nv_bfloat16* __restrict__ wl)
{
    __shared__ float tile[32][33];
    int m = blockIdx.z;
    const float* src = (m < 8) ? (qw + (size_t)m * DD * HD)
                               : (kvw + (size_t)(m - 8) * DD * HD);
    int jbase = (m < 8) ? (m << 8) : (2048 + ((m - 8) << 8));
    int d0 = blockIdx.x << 5, h0 = blockIdx.y << 5;
    int tx = threadIdx.x, ty = threadIdx.y;
#pragma unroll
    for (int i = 0; i < 4; i++) {
        int r = (ty << 2) + i;
        tile[r][tx] = src[(size_t)(d0 + r) * HD + h0 + tx];
    }
    __syncthreads();
#pragma unroll
    for (int i = 0; i < 4; i++) {
        int r = (ty << 2) + i;
        float v = tile[tx][r];
        __nv_bfloat16 h, l; bf16_split(v, h, l);
        size_t o = (size_t)(jbase + h0 + r) * DD + d0 + tx;
        wh[o] = h; wl[o] = l;
    }
}

// out weights: [2048=nh][2560=d] -> W2 [d][nh]
__global__ void transpose_outw_kernel(const float* __restrict__ ow,
                                      __nv_bfloat16* __restrict__ wh,
                                      __nv_bfloat16* __restrict__ wl)
{
    __shared__ float tile[32][33];
    int d0 = blockIdx.x << 5, n0 = blockIdx.y << 5;
    int tx = threadIdx.x, ty = threadIdx.y;
#pragma unroll
    for (int i = 0; i < 4; i++) {
        int r = (ty << 2) + i;
        tile[r][tx] = ow[(size_t)(n0 + r) * DD + d0 + tx];
    }
    __syncthreads();
#pragma unroll
    for (int i = 0; i < 4; i++) {
        int r = (ty << 2) + i;
        float v = tile[tx][r];
        __nv_bfloat16 h, l; bf16_split(v, h, l);
        size_t o = (size_t)(d0 + r) * 2048 + n0 + tx;
        wh[o] = h; wl[o] = l;
    }
}

// rope table: fp32 angle (matches reference), double range-reduction, fp32 sin/cos
__global__ void rope_table_kernel(const int* __restrict__ positions,
                                  float* __restrict__ st, float* __restrict__ ct)
{
    int idx = blockIdx.x * blockDim.x + threadIdx.x;   // 4096*128
    int t = idx >> 7;
    int i = idx & 127;
    float posf = (float)positions[t];
    float ts = (float)pow(10000.0, (double)i * (1.0 / 128.0));
    float ang = posf / ts;                         // fp32, like reference
    double da = (double)ang;
    double k = rint(da * 0.15915494309189533576888376337251);
    float rf = (float)(da - k * 6.2831853071795864769252867665590);
    st[idx] = sinf(rf);
    ct[idx] = cosf(rf);
}

// ================= mma.sync split-3 bf16 GEMM (unchanged from R11) =================
#define TSTRIDE 80
#define TBYTES  (128 * TSTRIDE)
#define STAGEB  (4 * TBYTES)
#define GEMM_SMEM (2 * STAGEB)

__device__ __forceinline__ void gemm_load_stage(
    uint32_t stage, int tid,
    const char* sAh, const char* sAl, const char* sBh, const char* sBl,
    size_t rowb, int k0b)
{
#pragma unroll
    for (int j = 0; j < 8; j++) {
        const char* sp = (j < 2) ? sAh : (j < 4) ? sAl : (j < 6) ? sBh : sBl;
        int idx = ((j & 1) << 8) + tid;
        int r = idx >> 2, c = idx & 3;
        uint32_t sdst = stage + (j >> 1) * TBYTES + r * TSTRIDE + (c << 4);
        cp16(sdst, sp + (size_t)r * rowb + k0b + (c << 4));
    }
    asm volatile("cp.async.commit_group;" ::: "memory");
}

__global__ __launch_bounds__(256) void mma_gemm_kernel(
    const __nv_bfloat16* __restrict__ Ahi, const __nv_bfloat16* __restrict__ Alo,
    const __nv_bfloat16* __restrict__ Bhi, const __nv_bfloat16* __restrict__ Blo,
    float* __restrict__ C, int ldc, int Kd)
{
    extern __shared__ char smem[];
    const uint32_t sbase = smem_u32(smem);
    const int tid = threadIdx.x;
    const int wid = tid >> 5, lane = tid & 31;
    const int warp_m = wid & 1, warp_n = wid >> 1;

    const int brow = blockIdx.y << 7;
    const int bcol = blockIdx.x << 7;
    const size_t rowb = (size_t)Kd * 2;
    const char* sAh = (const char*)Ahi + (size_t)brow * rowb;
    const char* sAl = (const char*)Alo + (size_t)brow * rowb;
    const char* sBh = (const char*)Bhi + (size_t)bcol * rowb;
    const char* sBl = (const char*)Blo + (size_t)bcol * rowb;

    const uint32_t rowA_off =
        (uint32_t)(warp_m * 64 + ((lane >> 3) & 1) * 8 + (lane & 7)) * TSTRIDE
        + ((lane >> 4) & 1) * 16;
    const uint32_t rowB_off =
        (uint32_t)(warp_n * 32 + ((lane >> 4) & 1) * 8 + (lane & 7)) * TSTRIDE
        + ((lane >> 3) & 1) * 16;

    float acc[4][4][4];
#pragma unroll
    for (int mt = 0; mt < 4; mt++)
#pragma unroll
        for (int nt = 0; nt < 4; nt++)
#pragma unroll
            for (int q = 0; q < 4; q++) acc[mt][nt][q] = 0.f;

    const int nsteps = Kd >> 5;
    gemm_load_stage(sbase, tid, sAh, sAl, sBh, sBl, rowb, 0);

    for (int s = 0; s < nsteps; s++) {
        if (s + 1 < nsteps) {
            gemm_load_stage(sbase + ((s + 1) & 1) * STAGEB, tid,
                            sAh, sAl, sBh, sBl, rowb, (s + 1) << 6);
            asm volatile("cp.async.wait_group 1;" ::: "memory");
        } else {
            asm volatile("cp.async.wait_group 0;" ::: "memory");
        }
        __syncthreads();

        const uint32_t stage = sbase + (s & 1) * STAGEB;
#pragma unroll
        for (int ks = 0; ks < 2; ks++) {
            uint32_t ah[4][4], al[4][4];
#pragma unroll
            for (int mt = 0; mt < 4; mt++) {
                uint32_t a = stage + rowA_off + mt * (16 * TSTRIDE) + ks * 32;
                ldmx4(ah[mt], a);
                ldmx4(al[mt], a + TBYTES);
            }
            uint32_t bh[2][4], bl[2][4];
#pragma unroll
            for (int p = 0; p < 2; p++) {
                uint32_t b = stage + 2 * TBYTES + rowB_off + p * (16 * TSTRIDE) + ks * 32;
                ldmx4(bh[p], b);
                ldmx4(bl[p], b + TBYTES);
            }
#pragma unroll
            for (int mt = 0; mt < 4; mt++)
#pragma unroll
                for (int nt = 0; nt < 4; nt++) {
                    const uint32_t* bhp = &bh[nt >> 1][(nt & 1) * 2];
                    const uint32_t* blp = &bl[nt >> 1][(nt & 1) * 2];
                    mma16816(acc[mt][nt], ah[mt], bhp);
                    mma16816(acc[mt][nt], ah[mt], blp);
                    mma16816(acc[mt][nt], al[mt], bhp);
                }
        }
        __syncthreads();
    }

    const int grp = lane >> 2, qid = lane & 3;
#pragma unroll
    for (int mt = 0; mt < 4; mt++) {
#pragma unroll
        for (int nt = 0; nt < 4; nt++) {
            int row = brow + warp_m * 64 + mt * 16 + grp;
            int col = bcol + warp_n * 32 + nt * 8 + qid * 2;
            *(float2*)&C[(size_t)row * ldc + col] =
                make_float2(acc[mt][nt][0], acc[mt][nt][1]);
            *(float2*)&C[(size_t)(row + 8) * ldc + col] =
                make_float2(acc[mt][nt][2], acc[mt][nt][3]);
        }
    }
}

// ================= RMSNorm + RoPE + bf16 split (one warp per (t,head-slot)) =================
// hh 0..7: q heads (norm+rope+1/16), 8..11: k heads (norm+rope), 12..15: v heads (split only)
__global__ void norm_rope_kernel(const float* __restrict__ qkv,
                                 const float* __restrict__ qns,
                                 const float* __restrict__ kns,
                                 const float* __restrict__ st,
                                 const float* __restrict__ ct,
                                 __nv_bfloat16* __restrict__ oh,
                                 __nv_bfloat16* __restrict__ ol)
{
    int g = blockIdx.x * 8 + (threadIdx.x >> 5);
    int lane = threadIdx.x & 31;
    int t = g >> 4;
    int hh = g & 15;
    int i4 = lane << 2;

    if (hh >= 12) {                                 // v: plain split
        int colbase = 3072 + ((hh - 12) << 8);
        const float* row = qkv + (size_t)t * 4096 + colbase;
        size_t ob = (size_t)t * 4096 + colbase;
#pragma unroll
        for (int half = 0; half < 2; half++) {
            float4 f = *(const float4*)&row[half * 128 + i4];
            float v[4] = { f.x, f.y, f.z, f.w };
            uint32_t hlo[2], llo[2];
#pragma unroll
            for (int p = 0; p < 2; p++) {
                __nv_bfloat16 h0, l0, h1, l1;
                bf16_split(v[p * 2], h0, l0);
                bf16_split(v[p * 2 + 1], h1, l1);
                hlo[p] = ((uint32_t)__bfloat16_as_ushort(h1) << 16) | __bfloat16_as_ushort(h0);
                llo[p] = ((uint32_t)__bfloat16_as_ushort(l1) << 16) | __bfloat16_as_ushort(l0);
            }
            *(uint2*)&oh[ob + half * 128 + i4] = make_uint2(hlo[0], hlo[1]);
            *(uint2*)&ol[ob + half * 128 + i4] = make_uint2(llo[0], llo[1]);
        }
        return;
    }

    bool isq = hh < 8;
    int colbase = isq ? (hh << 8) : (2048 + ((hh - 8) << 8));
    const float* sc = isq ? qns : kns;
    const float* row = qkv + (size_t)t * 4096 + colbase;

    float4 f = *(const float4*)&row[i4];
    float4 s = *(const float4*)&row[128 + i4];
    float ss = f.x * f.x + f.y * f.y + f.z * f.z + f.w * f.w
             + s.x * s.x + s.y * s.y + s.z * s.z + s.w * s.w;
#pragma unroll
    for (int off = 16; off; off >>= 1) ss += __shfl_xor_sync(0xffffffffu, ss, off);
    float mean = ss * (1.f / 256.f);
    float inv = (float)(1.0 / sqrt((double)mean + 1e-6));

    float4 scf = *(const float4*)&sc[i4];
    float4 scs = *(const float4*)&sc[128 + i4];
    float4 sa = *(const float4*)&st[(t << 7) + i4];
    float4 ca = *(const float4*)&ct[(t << 7) + i4];

    float fn[4] = { f.x * inv * (1.f + scf.x), f.y * inv * (1.f + scf.y),
                    f.z * inv * (1.f + scf.z), f.w * inv * (1.f + scf.w) };
    float sn[4] = { s.x * inv * (1.f + scs.x), s.y * inv * (1.f + scs.y),
                    s.z * inv * (1.f + scs.z), s.w * inv * (1.f + scs.w) };
    float saa[4] = { sa.x, sa.y, sa.z, sa.w };
    float caa[4] = { ca.x, ca.y, ca.z, ca.w };
    float qm = isq ? 0.0625f : 1.0f;
    float o1[4], o2[4];
#pragma unroll
    for (int k = 0; k < 4; k++) {
        o1[k] = (fn[k] * caa[k] - sn[k] * saa[k]) * qm;
        o2[k] = (sn[k] * caa[k] + fn[k] * saa[k]) * qm;
    }
    size_t ob = (size_t)t * 4096 + colbase;
    uint32_t h1lo[2], l1lo[2], h2lo[2], l2lo[2];
#pragma unroll
    for (int p = 0; p < 2; p++) {
        __nv_bfloat16 ha, la, hb, lb;
        bf16_split(o1[p * 2], ha, la); bf16_split(o1[p * 2 + 1], hb, lb);
        h1lo[p] = ((uint32_t)__bfloat16_as_ushort(hb) << 16) | __bfloat16_as_ushort(ha);
        l1lo[p] = ((uint32_t)__bfloat16_as_ushort(lb) << 16) | __bfloat16_as_ushort(la);
        bf16_split(o2[p * 2], ha, la); bf16_split(o2[p * 2 + 1], hb, lb);
        h2lo[p] = ((uint32_t)__bfloat16_as_ushort(hb) << 16) | __bfloat16_as_ushort(ha);
        l2lo[p] = ((uint32_t)__bfloat16_as_ushort(lb) << 16) | __bfloat16_as_ushort(la);
    }
    *(uint2*)&oh[ob + i4]       = make_uint2(h1lo[0], h1lo[1]);
    *(uint2*)&ol[ob + i4]       = make_uint2(l1lo[0], l1lo[1]);
    *(uint2*)&oh[ob + 128 + i4] = make_uint2(h2lo[0], h2lo[1]);
    *(uint2*)&ol[ob + 128 + i4] = make_uint2(l2lo[0], l2lo[1]);
}

// ================= tensor-core sliding-window flash attention =================
// BQ=64, BKV=32, 8 warps. S split-3 (Qh.Kh+Qh.Kl+Ql.Kh), PV split-3 (Ph.Vh+Ph.Vl+Pl.Vh).
#define QSTR 528                       // row stride bytes for Q/K/V smem tiles
#define O_QH 0
#define O_QL (O_QH + 64 * QSTR)
#define O_KH (O_QL + 64 * QSTR)
#define O_KL (O_KH + 32 * QSTR)
#define O_VH (O_KL + 32 * QSTR)
#define O_VL (O_VH + 32 * QSTR)
#define O_S  (O_VL + 32 * QSTR)        // 64 rows x 36 floats
#define O_PH (O_S + 64 * 144)
#define O_PL (O_PH + 64 * 80)
#define O_AL (O_PL + 64 * 80)
#define O_LL (O_AL + 256)
#define ATTN_SMEM (O_LL + 256)         // 155136

__global__ __launch_bounds__(256) void attn_kernel(
    const __nv_bfloat16* __restrict__ qkvh, const __nv_bfloat16* __restrict__ qkvl,
    __nv_bfloat16* __restrict__ ehi, __nv_bfloat16* __restrict__ elo)
{
    extern __shared__ char sm[];
    const uint32_t sb = smem_u32(sm);
    const int qt0  = blockIdx.x << 6;
    const int n    = blockIdx.y;
    const int kvh  = n >> 1;
    const int qcol = n << 8;
    const int kcol = 2048 + (kvh << 8);
    const int vcol = 3072 + (kvh << 8);
    const int tid = threadIdx.x;
    const int wid = tid >> 5, lane = tid & 31;
    const int warp_m = wid & 3;        // 16-row group
    const int warp_sn = wid >> 2;      // S: which 16-key half
    const int warp_vn = wid >> 2;      // PV: which 128-d half
    const int grp = lane >> 2, qid = lane & 3;
    const float NEGINF = __int_as_float(0xff800000u);

    // load Q (hi/lo)
    for (int u = tid; u < 2048; u += 256) {
        int r = u >> 5, c = (u & 31) << 4;
        size_t grow = (size_t)(qt0 + r) * 4096 + qcol;
        cp16(sb + O_QH + r * QSTR + c, (const char*)(qkvh + grow) + c);
        cp16(sb + O_QL + r * QSTR + c, (const char*)(qkvl + grow) + c);
    }
    asm volatile("cp.async.commit_group;\n\tcp.async.wait_group 0;" ::: "memory");

    // ldmatrix base addresses
    const uint32_t aQrow = (uint32_t)(warp_m * 16 + ((lane >> 3) & 1) * 8 + (lane & 7));
    const uint32_t aQhA = sb + O_QH + aQrow * QSTR + ((lane >> 4) & 1) * 16;
    const uint32_t aQlA = sb + O_QL + aQrow * QSTR + ((lane >> 4) & 1) * 16;
    const uint32_t bKkey = (uint32_t)(warp_sn * 16 + ((lane >> 4) & 1) * 8 + (lane & 7));
    const uint32_t bKhA = sb + O_KH + bKkey * QSTR + ((lane >> 3) & 1) * 16;
    const uint32_t bKlA = sb + O_KL + bKkey * QSTR + ((lane >> 3) & 1) * 16;
    const uint32_t aPhA = sb + O_PH + aQrow * 80 + ((lane >> 4) & 1) * 16;
    const uint32_t aPlA = sb + O_PL + aQrow * 80 + ((lane >> 4) & 1) * 16;
    const uint32_t bVkey = (uint32_t)(((lane >> 3) & 1) * 8 + (lane & 7));
    const uint32_t bVoff = (uint32_t)(warp_vn * 256) + ((lane >> 4) & 1) * 16;
    const uint32_t bVhA = sb + O_VH + bVkey * QSTR + bVoff;
    const uint32_t bVlA = sb + O_VL + bVkey * QSTR + bVoff;

    float accO[16][4];
#pragma unroll
    for (int nt = 0; nt < 16; nt++)
#pragma unroll
        for (int q = 0; q < 4; q++) accO[nt][q] = 0.f;

    // softmax thread state: row = tid>>2, quad lane sq = tid&3 (keys sq*8..sq*8+7)
    const int srow = tid >> 2, sq = tid & 3;
    float m_run = -1e30f, l_run = 0.f;
    float* sS = (float*)(sm + O_S);
    float* sAl = (float*)(sm + O_AL);
    float* sLl = (float*)(sm + O_LL);

    int s_lo = qt0 - (WIN - 1); if (s_lo < 0) s_lo = 0;
    int ks0 = s_lo & ~31;

    for (int ks = ks0; ks < qt0 + 64; ks += 32) {
        __syncthreads();   // prior PV readers done (also covers Q visibility, iter 0)
        for (int u = tid; u < 1024; u += 256) {
            int r = u >> 5, c = (u & 31) << 4;
            size_t grow = (size_t)(ks + r) * 4096;
            cp16(sb + O_KH + r * QSTR + c, (const char*)(qkvh + grow + kcol) + c);
            cp16(sb + O_KL + r * QSTR + c, (const char*)(qkvl + grow + kcol) + c);
            cp16(sb + O_VH + r * QSTR + c, (const char*)(qkvh + grow + vcol) + c);
            cp16(sb + O_VL + r * QSTR + c, (const char*)(qkvl + grow + vcol) + c);
        }
        asm volatile("cp.async.commit_group;\n\tcp.async.wait_group 0;" ::: "memory");
        __syncthreads();

        // ---- S = Q K^T (split-3), warp tile 16 rows x 16 keys ----
        float s0[4] = {0.f, 0.f, 0.f, 0.f}, s1[4] = {0.f, 0.f, 0.f, 0.f};
#pragma unroll
        for (int kk = 0; kk < 16; kk++) {
            uint32_t qh[4], ql[4], kh[4], kl[4];
            ldmx4(qh, aQhA + kk * 32);
            ldmx4(ql, aQlA + kk * 32);
            ldmx4(kh, bKhA + kk * 32);
            ldmx4(kl, bKlA + kk * 32);
            mma16816(s0, qh, &kh[0]); mma16816(s0, qh, &kl[0]); mma16816(s0, ql, &kh[0]);
            mma16816(s1, qh, &kh[2]); mma16816(s1, qh, &kl[2]); mma16816(s1, ql, &kh[2]);
        }
        {
            int r0 = warp_m * 16 + grp;
            int c0 = warp_sn * 16 + qid * 2;
            *(float2*)&sS[r0 * 36 + c0]           = make_float2(s0[0], s0[1]);
            *(float2*)&sS[(r0 + 8) * 36 + c0]     = make_float2(s0[2], s0[3]);
            *(float2*)&sS[r0 * 36 + c0 + 8]       = make_float2(s1[0], s1[1]);
            *(float2*)&sS[(r0 + 8) * 36 + c0 + 8] = make_float2(s1[2], s1[3]);
        }
        __syncthreads();

        // ---- online softmax (4 threads per row, 8 keys each) ----
        {
            float sv[8];
            const float* sp = &sS[srow * 36 + sq * 8];
            *(float4*)&sv[0] = *(const float4*)&sp[0];
            *(float4*)&sv[4] = *(const float4*)&sp[4];
            int tg = qt0 + srow;
            float mx = m_run;
#pragma unroll
            for (int j = 0; j < 8; j++) {
                int sg = ks + sq * 8 + j;
                bool ok = (sg <= tg) && (sg + WIN > tg);
                sv[j] = ok ? sv[j] : NEGINF;
                mx = fmaxf(mx, sv[j]);
            }
            mx = fmaxf(mx, __shfl_xor_sync(0xffffffffu, mx, 1));
            mx = fmaxf(mx, __shfl_xor_sync(0xffffffffu, mx, 2));
            float alpha = expf(m_run - mx);
            float psum = 0.f;
#pragma unroll
            for (int j = 0; j < 8; j += 2) {
                float p0 = expf(sv[j] - mx);
                float p1 = expf(sv[j + 1] - mx);
                psum += p0 + p1;
                __nv_bfloat16 h0, l0, h1, l1;
                bf16_split(p0, h0, l0);
                bf16_split(p1, h1, l1);
                uint32_t uh = ((uint32_t)__bfloat16_as_ushort(h1) << 16) | __bfloat16_as_ushort(h0);
                uint32_t ul = ((uint32_t)__bfloat16_as_ushort(l1) << 16) | __bfloat16_as_ushort(l0);
                int ob = srow * 80 + (sq * 8 + j) * 2;
                *(uint32_t*)(sm + O_PH + ob) = uh;
                *(uint32_t*)(sm + O_PL + ob) = ul;
            }
            psum += __shfl_xor_sync(0xffffffffu, psum, 1);
            psum += __shfl_xor_sync(0xffffffffu, psum, 2);
            l_run = l_run * alpha + psum;
            m_run = mx;
            if (sq == 0) { sAl[srow] = alpha; sLl[srow] = l_run; }
        }
        __syncthreads();

        // ---- PV: O = P V (split-3), warp tile 16 rows x 128 d ----
        {
            float a0 = sAl[warp_m * 16 + grp];
            float a1 = sAl[warp_m * 16 + grp + 8];
#pragma unroll
            for (int nt = 0; nt < 16; nt++) {
                accO[nt][0] *= a0; accO[nt][1] *= a0;
                accO[nt][2] *= a1; accO[nt][3] *= a1;
            }
#pragma unroll
            for (int kst = 0; kst < 2; kst++) {
                uint32_t ph_[4], pl_[4];
                ldmx4(ph_, aPhA + kst * 32);
                ldmx4(pl_, aPlA + kst * 32);
#pragma unroll
                for (int dt = 0; dt < 8; dt++) {
                    uint32_t vh_[4], vl_[4];
                    uint32_t va = kst * (16 * QSTR) + dt * 32;
                    ldmx4t(vh_, bVhA + va);
                    ldmx4t(vl_, bVlA + va);
                    mma16816(accO[dt * 2],     ph_, &vh_[0]);
                    mma16816(accO[dt * 2],     ph_, &vl_[0]);
                    mma16816(accO[dt * 2],     pl_, &vh_[0]);
                    mma16816(accO[dt * 2 + 1], ph_, &vh_[2]);
                    mma16816(accO[dt * 2 + 1], ph_, &vl_[2]);
                    mma16816(accO[dt * 2 + 1], pl_, &vh_[2]);
                }
            }
        }
    }

    // ---- epilogue: normalize and write bf16 hi/lo ENC ----
    float inv0 = 1.f / sLl[warp_m * 16 + grp];
    float inv1 = 1.f / sLl[warp_m * 16 + grp + 8];
    int row0 = qt0 + warp_m * 16 + grp;
#pragma unroll
    for (int nt = 0; nt < 16; nt++) {
        int dt = nt >> 1;
        int col = (n << 8) + warp_vn * 128 + dt * 16 + (nt & 1) * 8 + qid * 2;
        float v0 = accO[nt][0] * inv0, v1 = accO[nt][1] * inv0;
        float v2 = accO[nt][2] * inv1, v3 = accO[nt][3] * inv1;
        __nv_bfloat16 h0, l0, h1, l1;
        bf16_split(v0, h0, l0); bf16_split(v1, h1, l1);
        *(uint32_t*)&ehi[(size_t)row0 * 2048 + col] =
            ((uint32_t)__bfloat16_as_ushort(h1) << 16) | __bfloat16_as_ushort(h0);
        *(uint32_t*)&elo[(size_t)row0 * 2048 + col] =
            ((uint32_t)__bfloat16_as_ushort(l1) << 16) | __bfloat16_as_ushort(l0);
        bf16_split(v2, h0, l0); bf16_split(v3, h1, l1);
        *(uint32_t*)&ehi[(size_t)(row0 + 8) * 2048 + col] =
            ((uint32_t)__bfloat16_as_ushort(h1) << 16) | __bfloat16_as_ushort(h0);
        *(uint32_t*)&elo[(size_t)(row0 + 8) * 2048 + col] =
            ((uint32_t)__bfloat16_as_ushort(l1) << 16) | __bfloat16_as_ushort(l0);
    }
}

// ================= launch =================
extern "C" void kernel_launch(void* const* d_in, const int* in_sizes, int n_in,
                              void* d_out, int out_size)
{
    const float* x1   = (const float*)d_in[0];
    const float* x2   = (const float*)d_in[1];
    const float* qw   = (const float*)d_in[2];
    const float* kvw  = (const float*)d_in[3];
    const float* outw = (const float*)d_in[4];
    const float* qns  = (const float*)d_in[5];
    const float* kns  = (const float*)d_in[6];
    const int*   pos  = (const int*)d_in[7];
    float* out = (float*)d_out;

    float *pQKV, *pSIN, *pCOS;
    __nv_bfloat16 *pQKVh, *pQKVl, *pXh, *pXl, *pWh, *pWl, *pW2h, *pW2l, *pEh, *pEl;
    cudaGetSymbolAddress((void**)&pQKV,  g_QKV);
    cudaGetSymbolAddress((void**)&pQKVh, g_QKVh);
    cudaGetSymbolAddress((void**)&pQKVl, g_QKVl);
    cudaGetSymbolAddress((void**)&pSIN,  g_SIN);
    cudaGetSymbolAddress((void**)&pCOS,  g_COS);
    cudaGetSymbolAddress((void**)&pXh,   g_Xhi);
    cudaGetSymbolAddress((void**)&pXl,   g_Xlo);
    cudaGetSymbolAddress((void**)&pWh,   g_Whi);
    cudaGetSymbolAddress((void**)&pWl,   g_Wlo);
    cudaGetSymbolAddress((void**)&pW2h,  g_W2hi);
    cudaGetSymbolAddress((void**)&pW2l,  g_W2lo);
    cudaGetSymbolAddress((void**)&pEh,   g_Ehi);
    cudaGetSymbolAddress((void**)&pEl,   g_Elo);

    // prep
    convert_x_kernel<<<TT, 256>>>(x1, x2, pXh, pXl);
    transpose_qkvw_kernel<<<dim3(DD / 32, HD / 32, 16), dim3(32, 8)>>>(qw, kvw, pWh, pWl);
    transpose_outw_kernel<<<dim3(DD / 32, 2048 / 32), dim3(32, 8)>>>(outw, pW2h, pW2l);
    rope_table_kernel<<<(TT * 128) / 256, 256>>>(pos, pSIN, pCOS);

    // QKV projection (tensor cores, split-3)
    cudaFuncSetAttribute(mma_gemm_kernel, cudaFuncAttributeMaxDynamicSharedMemorySize,
                         GEMM_SMEM);
    mma_gemm_kernel<<<dim3(4096 / 128, TT / 128), 256, GEMM_SMEM>>>(
        pXh, pXl, pWh, pWl, pQKV, 4096, DD);

    // RMSNorm + RoPE + bf16 split (q,k normed+roped; v split only)
    norm_rope_kernel<<<(TT * 16) / 8, 256>>>(pQKV, qns, kns, pSIN, pCOS, pQKVh, pQKVl);

    // tensor-core sliding-window flash attention -> ENC bf16 hi/lo
    cudaFuncSetAttribute(attn_kernel, cudaFuncAttributeMaxDynamicSharedMemorySize,
                         ATTN_SMEM);
    attn_kernel<<<dim3(TT / 64, NH), 256, ATTN_SMEM>>>(pQKVh, pQKVl, pEh, pEl);

    // output projection (tensor cores, split-3)
    mma_gemm_kernel<<<dim3(DD / 128, TT / 128), 256, GEMM_SMEM>>>(
        pEh, pEl, pW2h, pW2l, out, DD, 2048);
}